// round 17
// baseline (speedup 1.0000x reference)
#include <cuda_runtime.h>
#include <cuda_fp16.h>
#include <cstdint>

constexpr int Bc = 4, Sc = 128, Hc = 32, Dc = 128, Tc = 2048;
constexpr int HD  = Hc * Dc;          // 4096
constexpr int KVB = 64;
constexpr int NT  = 512;              // threads

// smem layout (bytes)
constexpr uint32_t QTI  = 0;          // 128x128 fp16 = 32KB
constexpr uint32_t KTI  = 32768;      // 64x128 fp16 = 16KB
constexpr uint32_t VTI  = 49152;      // 16KB
// epilogue overlays: ored[128][128] fp32 = 64KB at 0 (Q/K/V dead), lred above
constexpr uint32_t LRED = 65536;
constexpr uint32_t SMEM_BYTES = 66560;    // 65KB

__device__ __forceinline__ uint32_t swz_w(int r, int d0) {   // 8B store addr (256B rows)
    return (uint32_t)(r * 256 + ((((d0 >> 3)) ^ (r & 7)) << 4) + ((d0 & 7) << 1));
}
__device__ __forceinline__ uint32_t swz_l(int r, int c0) {   // ldmatrix row addr (256B rows)
    return (uint32_t)(r * 256 + ((((c0 >> 3)) ^ (r & 7)) << 4));
}
__device__ __forceinline__ uint32_t smem_u32(const void* p) {
    uint32_t r;
    asm("{\n\t.reg .u64 t;\n\tcvta.to.shared.u64 t, %1;\n\tcvt.u32.u64 %0, t;\n\t}"
        : "=r"(r) : "l"(p));
    return r;
}

#define LDSM4(R0,R1,R2,R3,A) \
    asm volatile("ldmatrix.sync.aligned.m8n8.x4.shared.b16 {%0,%1,%2,%3}, [%4];" \
        : "=r"(R0),"=r"(R1),"=r"(R2),"=r"(R3) : "r"(A))
#define LDSM4T(R0,R1,R2,R3,A) \
    asm volatile("ldmatrix.sync.aligned.m8n8.x4.trans.shared.b16 {%0,%1,%2,%3}, [%4];" \
        : "=r"(R0),"=r"(R1),"=r"(R2),"=r"(R3) : "r"(A))
#define MMA(C,A0,A1,A2,A3,B0,B1) \
    asm volatile("mma.sync.aligned.m16n8k16.row.col.f32.f16.f16.f32 " \
        "{%0,%1,%2,%3}, {%4,%5,%6,%7}, {%8,%9}, {%0,%1,%2,%3};" \
        : "+f"((C)[0]),"+f"((C)[1]),"+f"((C)[2]),"+f"((C)[3]) \
        : "r"(A0),"r"(A1),"r"(A2),"r"(A3),"r"(B0),"r"(B1))

__device__ __forceinline__ uint32_t pk_us(unsigned short a, unsigned short b) {
    return (uint32_t)a | ((uint32_t)b << 16);
}
__device__ __forceinline__ uint2 cvt4h(float4 v) {
    return make_uint2(
        pk_us(__half_as_ushort(__float2half_rn(v.x)), __half_as_ushort(__float2half_rn(v.y))),
        pk_us(__half_as_ushort(__float2half_rn(v.z)), __half_as_ushort(__float2half_rn(v.w))));
}

__global__ void __launch_bounds__(NT, 1)
sdpa_h16r_kernel(const float* __restrict__ gq, const float* __restrict__ gk,
                 const float* __restrict__ gv, const float* __restrict__ gkc,
                 const float* __restrict__ gvc, const int* __restrict__ gpos,
                 float* __restrict__ gout)
{
    extern __shared__ char smc[];
    const uint32_t sb = smem_u32(smc);
    const int tid = threadIdx.x;
    const int wid = tid >> 5;
    const int l   = tid & 31;
    const int qt  = wid & 7;          // query tile (16 rows)
    const int s   = wid >> 3;         // key half (32 keys)
    const int bh = blockIdx.x, b = bh >> 5, h = bh & 31;

    const int start = *gpos;
    const int nkv   = start + Sc;
    const int nblk  = (nkv + KVB - 1) / KVB;

    const float* qb  = gq  + ((size_t)(b * Sc) * Hc + h) * Dc;
    const float* kcb = gkc + ((size_t)(b * Tc) * Hc + h) * Dc;
    const float* vcb = gvc + ((size_t)(b * Tc) * Hc + h) * Dc;
    const float* knb = gk  + ((size_t)(b * Sc) * Hc + h) * Dc;
    const float* vnb = gv  + ((size_t)(b * Sc) * Hc + h) * Dc;

    // per-thread K/V load coords (4 chunks: key = (tid>>5)+16*it, d = (tid&31)*4)
    const int lkey = tid >> 5;
    const int ld4  = (tid & 31) * 4;

    // ---- prologue: Q -> smem fp16, scale*log2(e) folded ----
    const float SCALE = 0.08838834764831845f * 1.4426950408889634f;
    #pragma unroll
    for (int it = 0; it < 8; it++) {
        int idx = tid + it * NT;
        int r = idx >> 5, d = (idx & 31) * 4;
        float4 qv = *(const float4*)(qb + (size_t)r * HD + d);
        qv.x *= SCALE; qv.y *= SCALE; qv.z *= SCALE; qv.w *= SCALE;
        *(uint2*)(smc + QTI + swz_w(r, d)) = cvt4h(qv);
    }
    // ---- block 0: LDG K/V -> convert -> tiles ----
    #pragma unroll
    for (int it = 0; it < 4; it++) {
        int key = lkey + it * 16;
        const float* ks = (key < start) ? kcb + (size_t)key * HD + ld4
                                        : knb + (size_t)(key - start) * HD + ld4;
        const float* vs = (key < start) ? vcb + (size_t)key * HD + ld4
                                        : vnb + (size_t)(key - start) * HD + ld4;
        uint32_t o = swz_w(key, ld4);
        *(uint2*)(smc + KTI + o) = cvt4h(*(const float4*)ks);
        *(uint2*)(smc + VTI + o) = cvt4h(*(const float4*)vs);
    }

    float O[16][4];
    #pragma unroll
    for (int t = 0; t < 16; t++) { O[t][0]=O[t][1]=O[t][2]=O[t][3]=0.f; }
    float lacc0 = 0.f, lacc1 = 0.f;

    // fragment address constants
    const int q0   = qt * 16;
    const int row0 = q0 + (l >> 2);
    const int qrow = q0 + (l & 15);
    const int qc8  = (l >> 4) << 3;
    const int krow = (l & 7) + ((l >> 4) << 3);
    const int kc8  = ((l >> 3) & 1) << 3;
    const int vrow = (l & 7) + (((l >> 3) & 1) << 3);
    const int vc8  = (l >> 4) << 3;
    const int colb = (l & 3) * 2;

    __syncthreads();   // publish Q + block 0 tiles

    for (int blk = 0; blk < nblk; blk++) {
        const int t0 = blk * KVB;
        const bool pf = (blk + 1) < nblk;

        // ---- issue K(next) LDG early (latency hidden under QK MMAs) ----
        float4 kreg[4];
        if (pf) {
            const int t0n = t0 + KVB;
            #pragma unroll
            for (int it = 0; it < 4; it++) {
                int jg = t0n + lkey + it * 16;
                kreg[it] = (jg < start) ? *(const float4*)(kcb + (size_t)jg * HD + ld4)
                                        : *(const float4*)(knb + (size_t)(jg - start) * HD + ld4);
            }
        }

        // ---- QK^T: this warp's 32-key half ----
        float S[4][4];
        #pragma unroll
        for (int t = 0; t < 4; t++) { S[t][0]=S[t][1]=S[t][2]=S[t][3]=0.f; }

        #pragma unroll
        for (int ks = 0; ks < 8; ks++) {
            int c0k = ks * 16 + kc8;
            uint32_t qh0,qh1,qh2,qh3;
            LDSM4(qh0,qh1,qh2,qh3, sb + QTI + swz_l(qrow, ks * 16 + qc8));
            uint32_t khf[2][4];
            #pragma unroll
            for (int np = 0; np < 2; np++) {
                uint32_t ko = swz_l(s * 32 + np * 16 + krow, c0k);
                LDSM4(khf[np][0],khf[np][1],khf[np][2],khf[np][3], sb + KTI + ko);
            }
            #pragma unroll
            for (int np = 0; np < 2; np++) {
                MMA(S[2*np  ], qh0,qh1,qh2,qh3, khf[np][0],khf[np][1]);
                MMA(S[2*np+1], qh0,qh1,qh2,qh3, khf[np][2],khf[np][3]);
            }
        }

        // ---- issue V(next) LDG (latency hidden under PV MMAs) ----
        float4 vreg[4];
        if (pf) {
            const int t0n = t0 + KVB;
            #pragma unroll
            for (int it = 0; it < 4; it++) {
                int jg = t0n + lkey + it * 16;
                vreg[it] = (jg < start) ? *(const float4*)(vcb + (size_t)jg * HD + ld4)
                                        : *(const float4*)(vnb + (size_t)(jg - start) * HD + ld4);
            }
        }

        // ---- softmax + P pack to fp16 A-fragments ----
        uint32_t ph[2][4];
        const bool needMask = (t0 + s * 32 + 31 - start) > q0;
        #pragma unroll
        for (int nt = 0; nt < 4; nt++) {
            float p0, p1, p2, p3;
            if (!needMask) {
                p0 = exp2f(S[nt][0]); p1 = exp2f(S[nt][1]);
                p2 = exp2f(S[nt][2]); p3 = exp2f(S[nt][3]);
            } else {
                int j0 = t0 + s * 32 + nt * 8 + colb - start;
                p0 = (j0     > row0    ) ? 0.f : exp2f(S[nt][0]);
                p1 = (j0 + 1 > row0    ) ? 0.f : exp2f(S[nt][1]);
                p2 = (j0     > row0 + 8) ? 0.f : exp2f(S[nt][2]);
                p3 = (j0 + 1 > row0 + 8) ? 0.f : exp2f(S[nt][3]);
            }
            lacc0 += p0 + p1;  lacc1 += p2 + p3;
            int kg = nt >> 1, sl = (nt & 1) * 2;
            ph[kg][sl  ] = pk_us(__half_as_ushort(__float2half_rn(p0)),
                                 __half_as_ushort(__float2half_rn(p1)));
            ph[kg][sl+1] = pk_us(__half_as_ushort(__float2half_rn(p2)),
                                 __half_as_ushort(__float2half_rn(p3)));
        }

        // ---- PV: this warp's 32 keys x ALL 128 d ----
        #pragma unroll
        for (int kg = 0; kg < 2; kg++) {
            int vr = s * 32 + kg * 16 + vrow;
            #pragma unroll
            for (int dq = 0; dq < 4; dq++) {
                uint32_t vh[2][4];
                #pragma unroll
                for (int u = 0; u < 2; u++) {
                    uint32_t vo = swz_l(vr, (dq * 2 + u) * 16 + vc8);
                    LDSM4T(vh[u][0],vh[u][1],vh[u][2],vh[u][3], sb + VTI + vo);
                }
                #pragma unroll
                for (int u = 0; u < 2; u++) {
                    MMA(O[2*(dq*2+u)  ], ph[kg][0],ph[kg][1],ph[kg][2],ph[kg][3], vh[u][0],vh[u][1]);
                    MMA(O[2*(dq*2+u)+1], ph[kg][0],ph[kg][1],ph[kg][2],ph[kg][3], vh[u][2],vh[u][3]);
                }
            }
        }

        // ---- rotate: barrier (reads done), convert regs -> tiles, barrier ----
        if (pf) {
            __syncthreads();
            #pragma unroll
            for (int it = 0; it < 4; it++) {
                int key = lkey + it * 16;
                uint32_t o = swz_w(key, ld4);
                *(uint2*)(smc + KTI + o) = cvt4h(kreg[it]);
                *(uint2*)(smc + VTI + o) = cvt4h(vreg[it]);
            }
            __syncthreads();          // publish new tiles
        }
    }

    // ---- epilogue: reduce l (quad), combine O + l across s halves ----
    lacc0 += __shfl_xor_sync(0xffffffffu, lacc0, 1);
    lacc0 += __shfl_xor_sync(0xffffffffu, lacc0, 2);
    lacc1 += __shfl_xor_sync(0xffffffffu, lacc1, 1);
    lacc1 += __shfl_xor_sync(0xffffffffu, lacc1, 2);

    float* ored = (float*)smc;            // Q/K/V region dead: [128][128] fp32
    float* lred = (float*)(smc + LRED);
    __syncthreads();                      // all warps past mainloop

    if (s == 1) {
        if ((l & 3) == 0) { lred[row0] = lacc0; lred[row0 + 8] = lacc1; }
        #pragma unroll
        for (int nt = 0; nt < 16; nt++) {
            int d = nt * 8 + colb;
            *(float2*)(ored + (size_t)row0 * 128 + d)       = make_float2(O[nt][0], O[nt][1]);
            *(float2*)(ored + (size_t)(row0 + 8) * 128 + d) = make_float2(O[nt][2], O[nt][3]);
        }
    }
    __syncthreads();
    if (s == 0) {
        const float inv0 = 1.f / (lacc0 + lred[row0]);
        const float inv1 = 1.f / (lacc1 + lred[row0 + 8]);
        float* o0 = gout + ((size_t)(b * Sc + row0    ) * HD) + h * Dc;
        float* o1 = gout + ((size_t)(b * Sc + row0 + 8) * HD) + h * Dc;
        #pragma unroll
        for (int nt = 0; nt < 16; nt++) {
            int d = nt * 8 + colb;
            float2 a0 = *(const float2*)(ored + (size_t)row0 * 128 + d);
            float2 a1 = *(const float2*)(ored + (size_t)(row0 + 8) * 128 + d);
            *(float2*)(o0 + d) = make_float2((O[nt][0] + a0.x) * inv0, (O[nt][1] + a0.y) * inv0);
            *(float2*)(o1 + d) = make_float2((O[nt][2] + a1.x) * inv1, (O[nt][3] + a1.y) * inv1);
        }
    }
}

extern "C" void kernel_launch(void* const* d_in, const int* in_sizes, int n_in,
                              void* d_out, int out_size)
{
    const float* q  = (const float*)d_in[0];
    const float* k  = (const float*)d_in[1];
    const float* v  = (const float*)d_in[2];
    const float* kc = (const float*)d_in[3];
    const float* vc = (const float*)d_in[4];
    const int*  pos = (const int*)d_in[5];
    float* out = (float*)d_out;

    cudaFuncSetAttribute(sdpa_h16r_kernel,
                         cudaFuncAttributeMaxDynamicSharedMemorySize, SMEM_BYTES);
    sdpa_h16r_kernel<<<Bc * Hc, NT, SMEM_BYTES>>>(q, k, v, kc, vc, pos, out);
}